// round 10
// baseline (speedup 1.0000x reference)
#include <cuda_runtime.h>
#include <cstdint>

#define NT    256
#define SCALE 0.17677669529663687f
#define SA    132
#define SP    65
#define SVS   68
#define HP    (64*SP)

// smem float offsets
#define OX    0            // 64x132  : X, later O
#define OQ    8448         // 64x132  : Q      } 128x132 -> Wp later
#define OK    16896        // 64x132  : K      }
#define OVT   25344        // 128x68  : V^T
#define OPW   34048        // 16896 f : W half-chunk double buffer / P (4x4160)
#define SMF   50944        // 203776 B

__device__ float g_BM[64 * 4 * 64 * 64];     // merged mask+bias [w][h][i][j]
__device__ float g_Wq[3 * 128 * SA];         // tf32 qkv_w, padded
__device__ float g_Wp[128 * SA];             // tf32 proj_w, padded

__device__ __forceinline__ float tf32r(float x) {
    float r; asm("cvt.rna.tf32.f32 %0, %1;" : "=f"(r) : "f"(x)); return r;
}
__device__ __forceinline__ void mma8(float* c, float a0, float a1, float a2, float a3,
                                     float b0, float b1) {
    asm volatile(
        "mma.sync.aligned.m16n8k8.row.col.f32.tf32.tf32.f32 "
        "{%0,%1,%2,%3}, {%4,%5,%6,%7}, {%8,%9}, {%0,%1,%2,%3};\n"
        : "+f"(c[0]), "+f"(c[1]), "+f"(c[2]), "+f"(c[3])
        : "r"(__float_as_uint(a0)), "r"(__float_as_uint(a1)),
          "r"(__float_as_uint(a2)), "r"(__float_as_uint(a3)),
          "r"(__float_as_uint(b0)), "r"(__float_as_uint(b1)));
}
__device__ __forceinline__ uint32_t smem_u32(const void* p) {
    uint32_t a;
    asm("{ .reg .u64 t; cvta.to.shared.u64 t, %1; cvt.u32.u64 %0, t; }" : "=r"(a) : "l"(p));
    return a;
}
__device__ __forceinline__ void cpa16(uint32_t dst, const void* src) {
    asm volatile("cp.async.cg.shared.global [%0], [%1], 16;" :: "r"(dst), "l"(src));
}
#define CP_COMMIT() asm volatile("cp.async.commit_group;" ::: "memory")
#define CP_WAIT(N)  asm volatile("cp.async.wait_group %0;" :: "n"(N) : "memory")

__global__ void prep_w(const float* __restrict__ qkv_w, const float* __restrict__ proj_w) {
    int gidx = blockIdx.x * 256 + threadIdx.x;
    int r = gidx >> 7, c = gidx & 127;
    if (r < 384) g_Wq[r * SA + c] = tf32r(qkv_w[r * 128 + c]);
    else         g_Wp[(r - 384) * SA + c] = tf32r(proj_w[(r - 384) * 128 + c]);
}
__global__ void prep_bm(const float* __restrict__ mask, const float* __restrict__ bias_table) {
    int w = blockIdx.x, h = blockIdx.y, t = threadIdx.x;
#pragma unroll
    for (int it = 0; it < 16; ++it) {
        int e = t + it * 256;
        int i = e >> 6, j = e & 63;
        int idx = ((i >> 3) - (j >> 3) + 7) * 15 + ((i & 7) - (j & 7) + 7);
        g_BM[(((w << 2) + h) << 12) + e] = mask[w * 4096 + e] + bias_table[idx * 4 + h];
    }
}

__global__ __launch_bounds__(NT, 1)
void winattn_mma(const float* __restrict__ x,
                 const float* __restrict__ qkv_b,
                 const float* __restrict__ proj_b,
                 float* __restrict__ out)
{
    extern __shared__ float sm[];
    const int tid  = threadIdx.x;
    const int wid  = tid >> 5, lane = tid & 31;
    const int g    = lane >> 2, t = lane & 3;
    const int b    = blockIdx.x;
    const uint32_t sb = smem_u32(sm);
    const int t2   = 2 * t;

    // ---- prologue: stream first two W half-chunks, load X ----
    {
#pragma unroll
        for (int e = tid; e < 2112; e += NT)
            cpa16(sb + OPW * 4 + e * 16, (const char*)g_Wq + e * 16);
        CP_COMMIT();
#pragma unroll
        for (int e = tid; e < 2112; e += NT)
            cpa16(sb + (OPW + 8448) * 4 + e * 16, (const char*)(g_Wq + 8448) + e * 16);
        CP_COMMIT();

        const float4* xg = (const float4*)(x + (size_t)b * 8192);
#pragma unroll
        for (int it = 0; it < 8; ++it) {
            int e = tid + it * NT;
            int row = e >> 5, c4 = (e & 31) * 4;
            float4 v = xg[e];
            float4 o; o.x = tf32r(v.x); o.y = tf32r(v.y); o.z = tf32r(v.z); o.w = tf32r(v.w);
            *(float4*)(sm + OX + row * SA + c4) = o;
        }
    }

    const int rg = wid & 3, ch = wid >> 2;   // QKV/proj mapping
    const int hh = wid & 3, rh = wid >> 2;   // attention mapping

    // ---- QKV: 6 half-chunks (64 cols each), pipelined ----
#pragma unroll
    for (int i = 0; i < 6; ++i) {
        if (i < 5) CP_WAIT(1); else CP_WAIT(0);
        __syncthreads();

        float c[4][4] = {};
        const float* A = sm + OX + (rg * 16) * SA;
        const float* B = sm + OPW + (i & 1) * 8448 + (ch * 32) * SA;
#pragma unroll
        for (int kk = 0; kk < 16; ++kk) {
            int k0 = kk * 8 + t2;
            float2 av0 = *(const float2*)(A + g * SA + k0);
            float2 av1 = *(const float2*)(A + (g + 8) * SA + k0);
#pragma unroll
            for (int n = 0; n < 4; ++n) {
                float2 bv = *(const float2*)(B + (n * 8 + g) * SA + k0);
                mma8(c[n], av0.x, av1.x, av0.y, av1.y, bv.x, bv.y);
            }
        }
#pragma unroll
        for (int n = 0; n < 4; ++n) {
            int col = ch * 32 + n * 8 + t2;
            float b0v = __ldg(qkv_b + i * 64 + col);
            float b1v = __ldg(qkv_b + i * 64 + col + 1);
            int tok = rg * 16 + g;
            if (i < 2) {
                int qc = i * 64 + col;
                sm[OQ + tok * SA + qc]           = tf32r((c[n][0] + b0v) * SCALE);
                sm[OQ + tok * SA + qc + 1]       = tf32r((c[n][1] + b1v) * SCALE);
                sm[OQ + (tok + 8) * SA + qc]     = tf32r((c[n][2] + b0v) * SCALE);
                sm[OQ + (tok + 8) * SA + qc + 1] = tf32r((c[n][3] + b1v) * SCALE);
            } else if (i < 4) {
                int kc = (i - 2) * 64 + col;
                sm[OK + tok * SA + kc]           = tf32r(c[n][0] + b0v);
                sm[OK + tok * SA + kc + 1]       = tf32r(c[n][1] + b1v);
                sm[OK + (tok + 8) * SA + kc]     = tf32r(c[n][2] + b0v);
                sm[OK + (tok + 8) * SA + kc + 1] = tf32r(c[n][3] + b1v);
            } else {
                int vd = (i - 4) * 64 + col;
                sm[OVT + vd * SVS + tok]           = tf32r(c[n][0] + b0v);
                sm[OVT + (vd + 1) * SVS + tok]     = tf32r(c[n][1] + b1v);
                sm[OVT + vd * SVS + tok + 8]       = tf32r(c[n][2] + b0v);
                sm[OVT + (vd + 1) * SVS + tok + 8] = tf32r(c[n][3] + b1v);
            }
        }
        __syncthreads();
        if (i + 2 < 6) {
#pragma unroll
            for (int e = tid; e < 2112; e += NT)
                cpa16(sb + (OPW + (i & 1) * 8448) * 4 + e * 16,
                      (const char*)(g_Wq + (i + 2) * 8448) + e * 16);
            CP_COMMIT();
        }
    }

    // ---- scores: warp=(head hh, row-half rh), tile 32x64 -> P smem ----
    {
        float c[2][8][4] = {};
        const float* A = sm + OQ + (rh * 32) * SA + hh * 32;
        const float* B = sm + OK + hh * 32;
#pragma unroll
        for (int kk = 0; kk < 4; ++kk) {
            int k0 = kk * 8 + t2;
            float2 a0[2], a1[2];
#pragma unroll
            for (int m = 0; m < 2; ++m) {
                a0[m] = *(const float2*)(A + (m * 16 + g) * SA + k0);
                a1[m] = *(const float2*)(A + (m * 16 + g + 8) * SA + k0);
            }
#pragma unroll
            for (int n = 0; n < 8; ++n) {
                float2 bv = *(const float2*)(B + (n * 8 + g) * SA + k0);
#pragma unroll
                for (int m = 0; m < 2; ++m)
                    mma8(c[m][n], a0[m].x, a1[m].x, a0[m].y, a1[m].y, bv.x, bv.y);
            }
        }
        float* sp = sm + OPW + hh * HP;
#pragma unroll
        for (int m = 0; m < 2; ++m)
#pragma unroll
            for (int n = 0; n < 8; ++n) {
                int i = rh * 32 + m * 16 + g, j = n * 8 + t2;
                sp[i * SP + j]           = c[m][n][0];
                sp[i * SP + j + 1]       = c[m][n][1];
                sp[(i + 8) * SP + j]     = c[m][n][2];
                sp[(i + 8) * SP + j + 1] = c[m][n][3];
            }
    }
    __syncthreads();

    // ---- prefetch Wp into OQ/OK region (dead after scores) ----
#pragma unroll
    for (int e = tid; e < 4224; e += NT)
        cpa16(sb + OQ * 4 + e * 16, (const char*)g_Wp + e * 16);
    CP_COMMIT();

    // ---- softmax: one (head,row) per thread; add merged bias+mask ----
    {
        int h = tid >> 6, i = tid & 63;
        float* srow = sm + OPW + h * HP + i * SP;
        const float4* bm4 = (const float4*)(g_BM + ((((b & 63) << 2) + h) << 12) + (i << 6));
        float v[64];
        float mx = -1e30f;
#pragma unroll
        for (int jj = 0; jj < 16; ++jj) {
            float4 m4 = bm4[jj];
            v[jj*4+0] = srow[jj*4+0] + m4.x;
            v[jj*4+1] = srow[jj*4+1] + m4.y;
            v[jj*4+2] = srow[jj*4+2] + m4.z;
            v[jj*4+3] = srow[jj*4+3] + m4.w;
            mx = fmaxf(mx, fmaxf(fmaxf(v[jj*4], v[jj*4+1]), fmaxf(v[jj*4+2], v[jj*4+3])));
        }
        float sum = 0.f;
#pragma unroll
        for (int j = 0; j < 64; ++j) { float e = __expf(v[j] - mx); v[j] = e; sum += e; }
        float inv = 1.0f / sum;
#pragma unroll
        for (int j = 0; j < 64; ++j) srow[j] = tf32r(v[j] * inv);
    }
    __syncthreads();

    // ---- AV: warp=(head hh, row-half rh), tile 32x32; O -> OX ----
    {
        float o[2][4][4] = {};
        const float* A = sm + OPW + hh * HP + (rh * 32) * SP;
        const float* B = sm + OVT + (hh * 32) * SVS;
#pragma unroll
        for (int kk = 0; kk < 8; ++kk) {
            int k0 = kk * 8 + t2;
            float a0[2], a1[2], a2[2], a3[2];
#pragma unroll
            for (int m = 0; m < 2; ++m) {   // SP odd -> scalar loads (alignment)
                const float* ap = A + (m * 16 + g) * SP + k0;
                a0[m] = ap[0]; a2[m] = ap[1];
                a1[m] = ap[8 * SP]; a3[m] = ap[8 * SP + 1];
            }
#pragma unroll
            for (int n = 0; n < 4; ++n) {
                float2 bv = *(const float2*)(B + (n * 8 + g) * SVS + k0);
#pragma unroll
                for (int m = 0; m < 2; ++m)
                    mma8(o[m][n], a0[m], a1[m], a2[m], a3[m], bv.x, bv.y);
            }
        }
#pragma unroll
        for (int m = 0; m < 2; ++m)
#pragma unroll
            for (int n = 0; n < 4; ++n) {
                int i = rh * 32 + m * 16 + g, d = hh * 32 + n * 8 + t2;
                sm[OX + i * SA + d]           = tf32r(o[m][n][0]);
                sm[OX + i * SA + d + 1]       = tf32r(o[m][n][1]);
                sm[OX + (i + 8) * SA + d]     = tf32r(o[m][n][2]);
                sm[OX + (i + 8) * SA + d + 1] = tf32r(o[m][n][3]);
            }
    }
    CP_WAIT(0);
    __syncthreads();

    // ---- proj: warp=(rg, ch), tile 16x64 ----
    {
        float cc[8][4] = {};
        const float* A = sm + OX + (rg * 16) * SA;
        const float* B = sm + OQ + (ch * 64) * SA;
#pragma unroll
        for (int kk = 0; kk < 16; ++kk) {
            int k0 = kk * 8 + t2;
            float2 av0 = *(const float2*)(A + g * SA + k0);
            float2 av1 = *(const float2*)(A + (g + 8) * SA + k0);
#pragma unroll
            for (int n = 0; n < 8; ++n) {
                float2 bv = *(const float2*)(B + (n * 8 + g) * SA + k0);
                mma8(cc[n], av0.x, av1.x, av0.y, av1.y, bv.x, bv.y);
            }
        }
#pragma unroll
        for (int n = 0; n < 8; ++n) {
            int col = ch * 64 + n * 8 + t2;
            float pb0 = __ldg(proj_b + col), pb1 = __ldg(proj_b + col + 1);
            int i = rg * 16 + g;
            float2 v0 = make_float2(cc[n][0] + pb0, cc[n][1] + pb1);
            float2 v1 = make_float2(cc[n][2] + pb0, cc[n][3] + pb1);
            *(float2*)(out + ((size_t)b * 64 + i) * 128 + col)     = v0;
            *(float2*)(out + ((size_t)b * 64 + i + 8) * 128 + col) = v1;
        }
    }
}

extern "C" void kernel_launch(void* const* d_in, const int* in_sizes, int n_in,
                              void* d_out, int out_size)
{
    const float* x          = (const float*)d_in[0];
    const float* mask       = (const float*)d_in[1];
    const float* qkv_w      = (const float*)d_in[2];
    const float* qkv_b      = (const float*)d_in[3];
    const float* proj_w     = (const float*)d_in[4];
    const float* proj_b     = (const float*)d_in[5];
    const float* bias_table = (const float*)d_in[6];
    float* out = (float*)d_out;

    prep_w<<<256, 256>>>(qkv_w, proj_w);
    prep_bm<<<dim3(64, 4), 256>>>(mask, bias_table);

    const int smem_bytes = SMF * 4;
    cudaFuncSetAttribute(winattn_mma,
                         cudaFuncAttributeMaxDynamicSharedMemorySize, smem_bytes);
    winattn_mma<<<4096, NT, smem_bytes>>>(x, qkv_b, proj_b, out);
}

// round 11
// speedup vs baseline: 1.9621x; 1.9621x over previous
#include <cuda_runtime.h>
#include <cstdint>

#define NT    256
#define SCALE 0.17677669529663687f
#define SA    132
#define SP    65
#define SVS   68
#define HP    (64*SP)

// smem float offsets
#define OX    0            // 64x132  : X, later O
#define OQ    8448         // 64x132  : Q      } 128x132 -> Wp later
#define OK    16896        // 64x132  : K      }
#define OVT   25344        // 128x68  : V^T
#define OPW   34048        // 16896 f : W half-chunk double buffer / P (4x4160)
#define SMF   50944        // 203776 B

__device__ float g_BM[64 * 4 * 64 * 64];     // merged mask+bias [w][h][i][j]
__device__ float g_Wq[3 * 128 * SA];         // tf32 qkv_w, padded
__device__ float g_Wp[128 * SA];             // tf32 proj_w, padded

__device__ __forceinline__ float tf32r(float x) {
    float r; asm("cvt.rna.tf32.f32 %0, %1;" : "=f"(r) : "f"(x)); return r;
}
__device__ __forceinline__ void mma8(float* c, uint32_t a0, uint32_t a1, uint32_t a2, uint32_t a3,
                                     uint32_t b0, uint32_t b1) {
    asm volatile(
        "mma.sync.aligned.m16n8k8.row.col.f32.tf32.tf32.f32 "
        "{%0,%1,%2,%3}, {%4,%5,%6,%7}, {%8,%9}, {%0,%1,%2,%3};\n"
        : "+f"(c[0]), "+f"(c[1]), "+f"(c[2]), "+f"(c[3])
        : "r"(a0), "r"(a1), "r"(a2), "r"(a3), "r"(b0), "r"(b1));
}
__device__ __forceinline__ uint32_t smem_u32(const void* p) {
    uint32_t a;
    asm("{ .reg .u64 t; cvta.to.shared.u64 t, %1; cvt.u32.u64 %0, t; }" : "=r"(a) : "l"(p));
    return a;
}
__device__ __forceinline__ void cpa16(uint32_t dst, const void* src) {
    asm volatile("cp.async.cg.shared.global [%0], [%1], 16;" :: "r"(dst), "l"(src));
}
#define CP_COMMIT() asm volatile("cp.async.commit_group;" ::: "memory")
#define CP_WAIT(N)  asm volatile("cp.async.wait_group %0;" :: "n"(N) : "memory")

__global__ void prep_w(const float* __restrict__ qkv_w, const float* __restrict__ proj_w) {
    int gidx = blockIdx.x * 256 + threadIdx.x;
    int r = gidx >> 7, c = gidx & 127;
    if (r < 384) g_Wq[r * SA + c] = tf32r(qkv_w[r * 128 + c]);
    else         g_Wp[(r - 384) * SA + c] = tf32r(proj_w[(r - 384) * 128 + c]);
}
__global__ void prep_bm(const float* __restrict__ mask, const float* __restrict__ bias_table) {
    int w = blockIdx.x, h = blockIdx.y, t = threadIdx.x;
#pragma unroll
    for (int it = 0; it < 16; ++it) {
        int e = t + it * 256;
        int i = e >> 6, j = e & 63;
        int idx = ((i >> 3) - (j >> 3) + 7) * 15 + ((i & 7) - (j & 7) + 7);
        g_BM[(((w << 2) + h) << 12) + e] = mask[w * 4096 + e] + bias_table[idx * 4 + h];
    }
}

__global__ __launch_bounds__(NT, 1)
void winattn_mma(const float* __restrict__ x,
                 const float* __restrict__ qkv_b,
                 const float* __restrict__ proj_b,
                 float* __restrict__ out)
{
    extern __shared__ float sm[];
    const int tid  = threadIdx.x;
    const int wid  = tid >> 5, lane = tid & 31;
    const int g    = lane >> 2, t = lane & 3;
    const int b    = blockIdx.x;
    const uint32_t sb = smem_u32(sm);

    // ---- prologue: stream first two W half-chunks, load X ----
    {
#pragma unroll
        for (int e = tid; e < 2112; e += NT)
            cpa16(sb + OPW * 4 + e * 16, (const char*)g_Wq + e * 16);
        CP_COMMIT();
#pragma unroll
        for (int e = tid; e < 2112; e += NT)
            cpa16(sb + (OPW + 8448) * 4 + e * 16, (const char*)(g_Wq + 8448) + e * 16);
        CP_COMMIT();

        const float4* xg = (const float4*)(x + (size_t)b * 8192);
#pragma unroll
        for (int it = 0; it < 8; ++it) {
            int e = tid + it * NT;
            int row = e >> 5, c4 = (e & 31) * 4;
            float4 v = xg[e];
            float4 o; o.x = tf32r(v.x); o.y = tf32r(v.y); o.z = tf32r(v.z); o.w = tf32r(v.w);
            *(float4*)(sm + OX + row * SA + c4) = o;
        }
    }

    const int rg = wid & 3, ch = wid >> 2;   // QKV/proj mapping
    const int hh = wid & 3, rh = wid >> 2;   // attention mapping

    // ---- QKV: 6 half-chunks (64 cols each), pipelined ----
#pragma unroll
    for (int i = 0; i < 6; ++i) {
        if (i < 5) CP_WAIT(1); else CP_WAIT(0);
        __syncthreads();

        float c[4][4] = {};
        const float* A = sm + OX + (rg * 16) * SA;
        const float* B = sm + OPW + (i & 1) * 8448 + (ch * 32) * SA;
#pragma unroll
        for (int kk = 0; kk < 16; ++kk) {
            int k0 = kk * 8;
            const float* ap = A + g * SA + k0 + t;
            uint32_t a0 = __float_as_uint(ap[0]);
            uint32_t a1 = __float_as_uint(ap[8 * SA]);
            uint32_t a2 = __float_as_uint(ap[4]);
            uint32_t a3 = __float_as_uint(ap[8 * SA + 4]);
#pragma unroll
            for (int n = 0; n < 4; ++n) {
                const float* bp = B + (n * 8 + g) * SA + k0 + t;
                mma8(c[n], a0, a1, a2, a3, __float_as_uint(bp[0]), __float_as_uint(bp[4]));
            }
        }
#pragma unroll
        for (int n = 0; n < 4; ++n) {
            int col = ch * 32 + n * 8 + 2 * t;
            float b0v = __ldg(qkv_b + i * 64 + col);
            float b1v = __ldg(qkv_b + i * 64 + col + 1);
            int tok = rg * 16 + g;
            if (i < 2) {
                int qc = i * 64 + col;
                sm[OQ + tok * SA + qc]           = tf32r((c[n][0] + b0v) * SCALE);
                sm[OQ + tok * SA + qc + 1]       = tf32r((c[n][1] + b1v) * SCALE);
                sm[OQ + (tok + 8) * SA + qc]     = tf32r((c[n][2] + b0v) * SCALE);
                sm[OQ + (tok + 8) * SA + qc + 1] = tf32r((c[n][3] + b1v) * SCALE);
            } else if (i < 4) {
                int kc = (i - 2) * 64 + col;
                sm[OK + tok * SA + kc]           = tf32r(c[n][0] + b0v);
                sm[OK + tok * SA + kc + 1]       = tf32r(c[n][1] + b1v);
                sm[OK + (tok + 8) * SA + kc]     = tf32r(c[n][2] + b0v);
                sm[OK + (tok + 8) * SA + kc + 1] = tf32r(c[n][3] + b1v);
            } else {
                int vd = (i - 4) * 64 + col;
                sm[OVT + vd * SVS + tok]           = tf32r(c[n][0] + b0v);
                sm[OVT + (vd + 1) * SVS + tok]     = tf32r(c[n][1] + b1v);
                sm[OVT + vd * SVS + tok + 8]       = tf32r(c[n][2] + b0v);
                sm[OVT + (vd + 1) * SVS + tok + 8] = tf32r(c[n][3] + b1v);
            }
        }
        __syncthreads();
        if (i + 2 < 6) {
#pragma unroll
            for (int e = tid; e < 2112; e += NT)
                cpa16(sb + (OPW + (i & 1) * 8448) * 4 + e * 16,
                      (const char*)(g_Wq + (i + 2) * 8448) + e * 16);
            CP_COMMIT();
        }
    }

    // ---- scores: warp=(head hh, row-half rh), tile 32x64 -> P smem ----
    {
        float c[2][8][4] = {};
        const float* A = sm + OQ + (rh * 32) * SA + hh * 32;
        const float* B = sm + OK + hh * 32;
#pragma unroll
        for (int kk = 0; kk < 4; ++kk) {
            int k0 = kk * 8;
            uint32_t a[2][4];
#pragma unroll
            for (int m = 0; m < 2; ++m) {
                const float* ap = A + (m * 16 + g) * SA + k0 + t;
                a[m][0] = __float_as_uint(ap[0]);
                a[m][1] = __float_as_uint(ap[8 * SA]);
                a[m][2] = __float_as_uint(ap[4]);
                a[m][3] = __float_as_uint(ap[8 * SA + 4]);
            }
#pragma unroll
            for (int n = 0; n < 8; ++n) {
                const float* bp = B + (n * 8 + g) * SA + k0 + t;
                uint32_t b0 = __float_as_uint(bp[0]), b1 = __float_as_uint(bp[4]);
#pragma unroll
                for (int m = 0; m < 2; ++m)
                    mma8(c[m][n], a[m][0], a[m][1], a[m][2], a[m][3], b0, b1);
            }
        }
        float* sp = sm + OPW + hh * HP;
#pragma unroll
        for (int m = 0; m < 2; ++m)
#pragma unroll
            for (int n = 0; n < 8; ++n) {
                int i = rh * 32 + m * 16 + g, j = n * 8 + 2 * t;
                sp[i * SP + j]           = c[m][n][0];
                sp[i * SP + j + 1]       = c[m][n][1];
                sp[(i + 8) * SP + j]     = c[m][n][2];
                sp[(i + 8) * SP + j + 1] = c[m][n][3];
            }
    }
    __syncthreads();

    // ---- prefetch Wp into OQ/OK region (dead after scores) ----
#pragma unroll
    for (int e = tid; e < 4224; e += NT)
        cpa16(sb + OQ * 4 + e * 16, (const char*)g_Wp + e * 16);
    CP_COMMIT();

    // ---- softmax: one (head,row) per thread; add merged bias+mask ----
    {
        int h = tid >> 6, i = tid & 63;
        float* srow = sm + OPW + h * HP + i * SP;
        const float4* bm4 = (const float4*)(g_BM + ((((b & 63) << 2) + h) << 12) + (i << 6));
        float v[64];
        float mx = -1e30f;
#pragma unroll
        for (int jj = 0; jj < 16; ++jj) {
            float4 m4 = bm4[jj];
            v[jj*4+0] = srow[jj*4+0] + m4.x;
            v[jj*4+1] = srow[jj*4+1] + m4.y;
            v[jj*4+2] = srow[jj*4+2] + m4.z;
            v[jj*4+3] = srow[jj*4+3] + m4.w;
            mx = fmaxf(mx, fmaxf(fmaxf(v[jj*4], v[jj*4+1]), fmaxf(v[jj*4+2], v[jj*4+3])));
        }
        float sum = 0.f;
#pragma unroll
        for (int j = 0; j < 64; ++j) { float e = __expf(v[j] - mx); v[j] = e; sum += e; }
        float inv = 1.0f / sum;
#pragma unroll
        for (int j = 0; j < 64; ++j) srow[j] = tf32r(v[j] * inv);
    }
    __syncthreads();

    // ---- AV: warp=(head hh, row-half rh), tile 32x32; O -> OX ----
    {
        float o[2][4][4] = {};
        const float* A = sm + OPW + hh * HP + (rh * 32) * SP;
        const float* B = sm + OVT + (hh * 32) * SVS;
#pragma unroll
        for (int kk = 0; kk < 8; ++kk) {
            int k0 = kk * 8;
            uint32_t a[2][4];
#pragma unroll
            for (int m = 0; m < 2; ++m) {
                const float* ap = A + (m * 16 + g) * SP + k0 + t;
                a[m][0] = __float_as_uint(ap[0]);
                a[m][1] = __float_as_uint(ap[8 * SP]);
                a[m][2] = __float_as_uint(ap[4]);
                a[m][3] = __float_as_uint(ap[8 * SP + 4]);
            }
#pragma unroll
            for (int n = 0; n < 4; ++n) {
                const float* bp = B + (n * 8 + g) * SVS + k0 + t;
                uint32_t b0 = __float_as_uint(bp[0]), b1 = __float_as_uint(bp[4]);
#pragma unroll
                for (int m = 0; m < 2; ++m)
                    mma8(o[m][n], a[m][0], a[m][1], a[m][2], a[m][3], b0, b1);
            }
        }
#pragma unroll
        for (int m = 0; m < 2; ++m)
#pragma unroll
            for (int n = 0; n < 4; ++n) {
                int i = rh * 32 + m * 16 + g, d = hh * 32 + n * 8 + 2 * t;
                sm[OX + i * SA + d]           = tf32r(o[m][n][0]);
                sm[OX + i * SA + d + 1]       = tf32r(o[m][n][1]);
                sm[OX + (i + 8) * SA + d]     = tf32r(o[m][n][2]);
                sm[OX + (i + 8) * SA + d + 1] = tf32r(o[m][n][3]);
            }
    }
    CP_WAIT(0);
    __syncthreads();

    // ---- proj: warp=(rg, ch), tile 16x64 ----
    {
        float cc[8][4] = {};
        const float* A = sm + OX + (rg * 16) * SA;
        const float* B = sm + OQ + (ch * 64) * SA;
#pragma unroll
        for (int kk = 0; kk < 16; ++kk) {
            int k0 = kk * 8;
            const float* ap = A + g * SA + k0 + t;
            uint32_t a0 = __float_as_uint(ap[0]);
            uint32_t a1 = __float_as_uint(ap[8 * SA]);
            uint32_t a2 = __float_as_uint(ap[4]);
            uint32_t a3 = __float_as_uint(ap[8 * SA + 4]);
#pragma unroll
            for (int n = 0; n < 8; ++n) {
                const float* bp = B + (n * 8 + g) * SA + k0 + t;
                mma8(cc[n], a0, a1, a2, a3, __float_as_uint(bp[0]), __float_as_uint(bp[4]));
            }
        }
#pragma unroll
        for (int n = 0; n < 8; ++n) {
            int col = ch * 64 + n * 8 + 2 * t;
            float pb0 = __ldg(proj_b + col), pb1 = __ldg(proj_b + col + 1);
            int i = rg * 16 + g;
            float2 v0 = make_float2(cc[n][0] + pb0, cc[n][1] + pb1);
            float2 v1 = make_float2(cc[n][2] + pb0, cc[n][3] + pb1);
            *(float2*)(out + ((size_t)b * 64 + i) * 128 + col)     = v0;
            *(float2*)(out + ((size_t)b * 64 + i + 8) * 128 + col) = v1;
        }
    }
}

extern "C" void kernel_launch(void* const* d_in, const int* in_sizes, int n_in,
                              void* d_out, int out_size)
{
    const float* x          = (const float*)d_in[0];
    const float* mask       = (const float*)d_in[1];
    const float* qkv_w      = (const float*)d_in[2];
    const float* qkv_b      = (const float*)d_in[3];
    const float* proj_w     = (const float*)d_in[4];
    const float* proj_b     = (const float*)d_in[5];
    const float* bias_table = (const float*)d_in[6];
    float* out = (float*)d_out;

    prep_w<<<256, 256>>>(qkv_w, proj_w);
    prep_bm<<<dim3(64, 4), 256>>>(mask, bias_table);

    const int smem_bytes = SMF * 4;
    cudaFuncSetAttribute(winattn_mma,
                         cudaFuncAttributeMaxDynamicSharedMemorySize, smem_bytes);
    winattn_mma<<<4096, NT, smem_bytes>>>(x, qkv_b, proj_b, out);
}

// round 16
// speedup vs baseline: 2.1283x; 1.0847x over previous
#include <cuda_runtime.h>
#include <cstdint>

#define NT    256
#define SCALE 0.17677669529663687f
#define SA    132
#define SP    65
#define SVS   68
#define HP    (64*SP)

// smem float offsets
#define OX    0            // 64x132  : X, later O
#define OQ    8448         // 64x132  : Q      } 128x132 -> Wp later
#define OK    16896        // 64x132  : K      }
#define OVT   25344        // 128x68  : V^T
#define OPW   34048        // 16896 f : W half-chunk double buffer / P (4x4160)
#define SMF   50944        // 203776 B

__device__ float g_BM[64 * 4 * 64 * 64];     // merged mask+bias [w][h][i][j]
__device__ float g_Wq[3 * 128 * SA];         // tf32 qkv_w, padded
__device__ float g_Wp[128 * SA];             // tf32 proj_w, padded

__device__ __forceinline__ float tf32r(float x) {
    float r; asm("cvt.rna.tf32.f32 %0, %1;" : "=f"(r) : "f"(x)); return r;
}
__device__ __forceinline__ void mma8(float* c, uint32_t a0, uint32_t a1, uint32_t a2, uint32_t a3,
                                     uint32_t b0, uint32_t b1) {
    asm volatile(
        "mma.sync.aligned.m16n8k8.row.col.f32.tf32.tf32.f32 "
        "{%0,%1,%2,%3}, {%4,%5,%6,%7}, {%8,%9}, {%0,%1,%2,%3};\n"
        : "+f"(c[0]), "+f"(c[1]), "+f"(c[2]), "+f"(c[3])
        : "r"(a0), "r"(a1), "r"(a2), "r"(a3), "r"(b0), "r"(b1));
}
__device__ __forceinline__ uint32_t smem_u32(const void* p) {
    uint32_t a;
    asm("{ .reg .u64 t; cvta.to.shared.u64 t, %1; cvt.u32.u64 %0, t; }" : "=r"(a) : "l"(p));
    return a;
}
__device__ __forceinline__ void cpa16(uint32_t dst, const void* src) {
    asm volatile("cp.async.cg.shared.global [%0], [%1], 16;" :: "r"(dst), "l"(src));
}
#define CP_COMMIT() asm volatile("cp.async.commit_group;" ::: "memory")
#define CP_WAIT(N)  asm volatile("cp.async.wait_group %0;" :: "n"(N) : "memory")

__global__ void prep_w(const float* __restrict__ qkv_w, const float* __restrict__ proj_w) {
    int gidx = blockIdx.x * 256 + threadIdx.x;
    int r = gidx >> 7, c = gidx & 127;
    if (r < 384) g_Wq[r * SA + c] = tf32r(qkv_w[r * 128 + c]);
    else         g_Wp[(r - 384) * SA + c] = tf32r(proj_w[(r - 384) * 128 + c]);
}
__global__ void prep_bm(const float* __restrict__ mask, const float* __restrict__ bias_table) {
    int w = blockIdx.x, h = blockIdx.y, t = threadIdx.x;
#pragma unroll
    for (int it = 0; it < 16; ++it) {
        int e = t + it * 256;
        int i = e >> 6, j = e & 63;
        int idx = ((i >> 3) - (j >> 3) + 7) * 15 + ((i & 7) - (j & 7) + 7);
        g_BM[(((w << 2) + h) << 12) + e] = mask[w * 4096 + e] + bias_table[idx * 4 + h];
    }
}

__global__ __launch_bounds__(NT, 1)
void winattn_mma(const float* __restrict__ x,
                 const float* __restrict__ qkv_b,
                 const float* __restrict__ proj_b,
                 float* __restrict__ out)
{
    extern __shared__ float sm[];
    const int tid  = threadIdx.x;
    const int wid  = tid >> 5, lane = tid & 31;
    const int g    = lane >> 2, t = lane & 3;
    const int b    = blockIdx.x;
    const uint32_t sb = smem_u32(sm);

    // ---- prologue: stream first two W half-chunks, load X ----
    {
#pragma unroll
        for (int e = tid; e < 2112; e += NT)
            cpa16(sb + OPW * 4 + e * 16, (const char*)g_Wq + e * 16);
        CP_COMMIT();
#pragma unroll
        for (int e = tid; e < 2112; e += NT)
            cpa16(sb + (OPW + 8448) * 4 + e * 16, (const char*)(g_Wq + 8448) + e * 16);
        CP_COMMIT();

        const float4* xg = (const float4*)(x + (size_t)b * 8192);
#pragma unroll
        for (int it = 0; it < 8; ++it) {
            int e = tid + it * NT;
            int row = e >> 5, c4 = (e & 31) * 4;
            float4 v = xg[e];
            float4 o; o.x = tf32r(v.x); o.y = tf32r(v.y); o.z = tf32r(v.z); o.w = tf32r(v.w);
            *(float4*)(sm + OX + row * SA + c4) = o;
        }
    }

    const int rg = wid & 3, ch = wid >> 2;   // QKV/proj mapping
    const int hh = wid & 3, rh = wid >> 2;   // attention mapping

    uint32_t af[16][4];                      // X fragments, resident across all 6 chunks

    // ---- QKV: 6 half-chunks (64 cols each), pipelined ----
#pragma unroll
    for (int i = 0; i < 6; ++i) {
        if (i < 5) CP_WAIT(1); else CP_WAIT(0);
        __syncthreads();

        if (i == 0) {    // load A fragments once (X visible after this barrier)
            const float* Ax = sm + OX + (rg * 16) * SA;
#pragma unroll
            for (int kk = 0; kk < 16; ++kk) {
                const float* ap = Ax + g * SA + kk * 8 + t;
                af[kk][0] = __float_as_uint(ap[0]);
                af[kk][1] = __float_as_uint(ap[8 * SA]);
                af[kk][2] = __float_as_uint(ap[4]);
                af[kk][3] = __float_as_uint(ap[8 * SA + 4]);
            }
        }

        float c[4][4] = {};
        const float* B = sm + OPW + (i & 1) * 8448 + (ch * 32) * SA;
#pragma unroll
        for (int kk = 0; kk < 16; ++kk) {
            int k0 = kk * 8;
#pragma unroll
            for (int n = 0; n < 4; ++n) {
                const float* bp = B + (n * 8 + g) * SA + k0 + t;
                mma8(c[n], af[kk][0], af[kk][1], af[kk][2], af[kk][3],
                     __float_as_uint(bp[0]), __float_as_uint(bp[4]));
            }
        }
#pragma unroll
        for (int n = 0; n < 4; ++n) {
            int col = ch * 32 + n * 8 + 2 * t;
            float b0v = __ldg(qkv_b + i * 64 + col);
            float b1v = __ldg(qkv_b + i * 64 + col + 1);
            int tok = rg * 16 + g;
            if (i < 2) {
                int qc = i * 64 + col;
                sm[OQ + tok * SA + qc]           = tf32r((c[n][0] + b0v) * SCALE);
                sm[OQ + tok * SA + qc + 1]       = tf32r((c[n][1] + b1v) * SCALE);
                sm[OQ + (tok + 8) * SA + qc]     = tf32r((c[n][2] + b0v) * SCALE);
                sm[OQ + (tok + 8) * SA + qc + 1] = tf32r((c[n][3] + b1v) * SCALE);
            } else if (i < 4) {
                int kc = (i - 2) * 64 + col;
                sm[OK + tok * SA + kc]           = tf32r(c[n][0] + b0v);
                sm[OK + tok * SA + kc + 1]       = tf32r(c[n][1] + b1v);
                sm[OK + (tok + 8) * SA + kc]     = tf32r(c[n][2] + b0v);
                sm[OK + (tok + 8) * SA + kc + 1] = tf32r(c[n][3] + b1v);
            } else {
                int vd = (i - 4) * 64 + col;
                sm[OVT + vd * SVS + tok]           = tf32r(c[n][0] + b0v);
                sm[OVT + (vd + 1) * SVS + tok]     = tf32r(c[n][1] + b1v);
                sm[OVT + vd * SVS + tok + 8]       = tf32r(c[n][2] + b0v);
                sm[OVT + (vd + 1) * SVS + tok + 8] = tf32r(c[n][3] + b1v);
            }
        }
        __syncthreads();
        if (i + 2 < 6) {
#pragma unroll
            for (int e = tid; e < 2112; e += NT)
                cpa16(sb + (OPW + (i & 1) * 8448) * 4 + e * 16,
                      (const char*)(g_Wq + (i + 2) * 8448) + e * 16);
            CP_COMMIT();
        }
    }

    // ---- scores: warp=(head hh, row-half rh), tile 32x64 -> P smem ----
    {
        float c[2][8][4] = {};
        const float* A = sm + OQ + (rh * 32) * SA + hh * 32;
        const float* B = sm + OK + hh * 32;
#pragma unroll
        for (int kk = 0; kk < 4; ++kk) {
            int k0 = kk * 8;
            uint32_t a[2][4];
#pragma unroll
            for (int m = 0; m < 2; ++m) {
                const float* ap = A + (m * 16 + g) * SA + k0 + t;
                a[m][0] = __float_as_uint(ap[0]);
                a[m][1] = __float_as_uint(ap[8 * SA]);
                a[m][2] = __float_as_uint(ap[4]);
                a[m][3] = __float_as_uint(ap[8 * SA + 4]);
            }
#pragma unroll
            for (int n = 0; n < 8; ++n) {
                const float* bp = B + (n * 8 + g) * SA + k0 + t;
                uint32_t b0 = __float_as_uint(bp[0]), b1 = __float_as_uint(bp[4]);
#pragma unroll
                for (int m = 0; m < 2; ++m)
                    mma8(c[m][n], a[m][0], a[m][1], a[m][2], a[m][3], b0, b1);
            }
        }
        float* sp = sm + OPW + hh * HP;
#pragma unroll
        for (int m = 0; m < 2; ++m)
#pragma unroll
            for (int n = 0; n < 8; ++n) {
                int i = rh * 32 + m * 16 + g, j = n * 8 + 2 * t;
                sp[i * SP + j]           = c[m][n][0];
                sp[i * SP + j + 1]       = c[m][n][1];
                sp[(i + 8) * SP + j]     = c[m][n][2];
                sp[(i + 8) * SP + j + 1] = c[m][n][3];
            }
    }
    __syncthreads();

    // ---- prefetch Wp into OQ/OK region (dead after scores) ----
#pragma unroll
    for (int e = tid; e < 4224; e += NT)
        cpa16(sb + OQ * 4 + e * 16, (const char*)g_Wp + e * 16);
    CP_COMMIT();

    // ---- softmax: one (head,row) per thread; add merged bias+mask ----
    {
        int h = tid >> 6, i = tid & 63;
        float* srow = sm + OPW + h * HP + i * SP;
        const float4* bm4 = (const float4*)(g_BM + ((((b & 63) << 2) + h) << 12) + (i << 6));
        float v[64];
        float mx = -1e30f;
#pragma unroll
        for (int jj = 0; jj < 16; ++jj) {
            float4 m4 = bm4[jj];
            v[jj*4+0] = srow[jj*4+0] + m4.x;
            v[jj*4+1] = srow[jj*4+1] + m4.y;
            v[jj*4+2] = srow[jj*4+2] + m4.z;
            v[jj*4+3] = srow[jj*4+3] + m4.w;
            mx = fmaxf(mx, fmaxf(fmaxf(v[jj*4], v[jj*4+1]), fmaxf(v[jj*4+2], v[jj*4+3])));
        }
        float sum = 0.f;
#pragma unroll
        for (int j = 0; j < 64; ++j) { float e = __expf(v[j] - mx); v[j] = e; sum += e; }
        float inv = 1.0f / sum;
#pragma unroll
        for (int j = 0; j < 64; ++j) srow[j] = tf32r(v[j] * inv);
    }
    __syncthreads();

    // ---- AV: warp=(head hh, row-half rh), tile 32x32; O -> OX ----
    {
        float o[2][4][4] = {};
        const float* A = sm + OPW + hh * HP + (rh * 32) * SP;
        const float* B = sm + OVT + (hh * 32) * SVS;
#pragma unroll
        for (int kk = 0; kk < 8; ++kk) {
            int k0 = kk * 8;
            uint32_t a[2][4];
#pragma unroll
            for (int m = 0; m < 2; ++m) {
                const float* ap = A + (m * 16 + g) * SP + k0 + t;
                a[m][0] = __float_as_uint(ap[0]);
                a[m][1] = __float_as_uint(ap[8 * SP]);
                a[m][2] = __float_as_uint(ap[4]);
                a[m][3] = __float_as_uint(ap[8 * SP + 4]);
            }
#pragma unroll
            for (int n = 0; n < 4; ++n) {
                const float* bp = B + (n * 8 + g) * SVS + k0 + t;
                uint32_t b0 = __float_as_uint(bp[0]), b1 = __float_as_uint(bp[4]);
#pragma unroll
                for (int m = 0; m < 2; ++m)
                    mma8(o[m][n], a[m][0], a[m][1], a[m][2], a[m][3], b0, b1);
            }
        }
#pragma unroll
        for (int m = 0; m < 2; ++m)
#pragma unroll
            for (int n = 0; n < 4; ++n) {
                int i = rh * 32 + m * 16 + g, d = hh * 32 + n * 8 + 2 * t;
                sm[OX + i * SA + d]           = tf32r(o[m][n][0]);
                sm[OX + i * SA + d + 1]       = tf32r(o[m][n][1]);
                sm[OX + (i + 8) * SA + d]     = tf32r(o[m][n][2]);
                sm[OX + (i + 8) * SA + d + 1] = tf32r(o[m][n][3]);
            }
    }
    CP_WAIT(0);
    __syncthreads();

    // ---- proj: warp=(rg, ch), tile 16x64 ----
    {
        float cc[8][4] = {};
        const float* A = sm + OX + (rg * 16) * SA;
        const float* B = sm + OQ + (ch * 64) * SA;
#pragma unroll
        for (int kk = 0; kk < 16; ++kk) {
            int k0 = kk * 8;
            const float* ap = A + g * SA + k0 + t;
            uint32_t a0 = __float_as_uint(ap[0]);
            uint32_t a1 = __float_as_uint(ap[8 * SA]);
            uint32_t a2 = __float_as_uint(ap[4]);
            uint32_t a3 = __float_as_uint(ap[8 * SA + 4]);
#pragma unroll
            for (int n = 0; n < 8; ++n) {
                const float* bp = B + (n * 8 + g) * SA + k0 + t;
                mma8(cc[n], a0, a1, a2, a3, __float_as_uint(bp[0]), __float_as_uint(bp[4]));
            }
        }
#pragma unroll
        for (int n = 0; n < 8; ++n) {
            int col = ch * 64 + n * 8 + 2 * t;
            float pb0 = __ldg(proj_b + col), pb1 = __ldg(proj_b + col + 1);
            int i = rg * 16 + g;
            float2 v0 = make_float2(cc[n][0] + pb0, cc[n][1] + pb1);
            float2 v1 = make_float2(cc[n][2] + pb0, cc[n][3] + pb1);
            *(float2*)(out + ((size_t)b * 64 + i) * 128 + col)     = v0;
            *(float2*)(out + ((size_t)b * 64 + i + 8) * 128 + col) = v1;
        }
    }
}

extern "C" void kernel_launch(void* const* d_in, const int* in_sizes, int n_in,
                              void* d_out, int out_size)
{
    const float* x          = (const float*)d_in[0];
    const float* mask       = (const float*)d_in[1];
    const float* qkv_w      = (const float*)d_in[2];
    const float* qkv_b      = (const float*)d_in[3];
    const float* proj_w     = (const float*)d_in[4];
    const float* proj_b     = (const float*)d_in[5];
    const float* bias_table = (const float*)d_in[6];
    float* out = (float*)d_out;

    prep_w<<<256, 256>>>(qkv_w, proj_w);
    prep_bm<<<dim3(64, 4), 256>>>(mask, bias_table);

    const int smem_bytes = SMF * 4;   // 203776
    cudaFuncSetAttribute(winattn_mma,
                         cudaFuncAttributeMaxDynamicSharedMemorySize, smem_bytes);
    winattn_mma<<<4096, NT, smem_bytes>>>(x, qkv_b, proj_b, out);
}

// round 17
// speedup vs baseline: 2.6785x; 1.2585x over previous
#include <cuda_runtime.h>
#include <cstdint>

#define NT    256
#define SCALE 0.17677669529663687f
#define SA    132
#define SVS   72          // ≡ 8 (mod 32) floats -> conflict-free float2 loads at +2t

// smem float offsets
#define OX    0            // 64x132  : X, later O
#define OQ    8448         // 64x132  : Q      } 128x132 -> Wp later
#define OK    16896        // 64x132  : K      }
#define OVT   25344        // 128x72  : V^T
#define OPW   34560        // 16896 f : W half-chunk double buffer
#define SMF   51456        // 205824 B

__device__ float g_BM[64 * 4 * 64 * 64];     // merged mask+bias [w][h][i][j]
__device__ float g_Wq[3 * 128 * SA];         // tf32 qkv_w, padded
__device__ float g_Wp[128 * SA];             // tf32 proj_w, padded

__device__ __forceinline__ float tf32r(float x) {
    float r; asm("cvt.rna.tf32.f32 %0, %1;" : "=f"(r) : "f"(x)); return r;
}
__device__ __forceinline__ void mma8(float* c, uint32_t a0, uint32_t a1, uint32_t a2, uint32_t a3,
                                     uint32_t b0, uint32_t b1) {
    asm volatile(
        "mma.sync.aligned.m16n8k8.row.col.f32.tf32.tf32.f32 "
        "{%0,%1,%2,%3}, {%4,%5,%6,%7}, {%8,%9}, {%0,%1,%2,%3};\n"
        : "+f"(c[0]), "+f"(c[1]), "+f"(c[2]), "+f"(c[3])
        : "r"(a0), "r"(a1), "r"(a2), "r"(a3), "r"(b0), "r"(b1));
}
__device__ __forceinline__ void mma8f(float* c, float a0, float a1, float a2, float a3,
                                      float b0, float b1) {
    mma8(c, __float_as_uint(a0), __float_as_uint(a1), __float_as_uint(a2),
         __float_as_uint(a3), __float_as_uint(b0), __float_as_uint(b1));
}
__device__ __forceinline__ uint32_t smem_u32(const void* p) {
    uint32_t a;
    asm("{ .reg .u64 t; cvta.to.shared.u64 t, %1; cvt.u32.u64 %0, t; }" : "=r"(a) : "l"(p));
    return a;
}
__device__ __forceinline__ void cpa16(uint32_t dst, const void* src) {
    asm volatile("cp.async.cg.shared.global [%0], [%1], 16;" :: "r"(dst), "l"(src));
}
#define CP_COMMIT() asm volatile("cp.async.commit_group;" ::: "memory")
#define CP_WAIT(N)  asm volatile("cp.async.wait_group %0;" :: "n"(N) : "memory")

__global__ void prep_w(const float* __restrict__ qkv_w, const float* __restrict__ proj_w) {
    int gidx = blockIdx.x * 256 + threadIdx.x;
    int r = gidx >> 7, c = gidx & 127;
    if (r < 384) g_Wq[r * SA + c] = tf32r(qkv_w[r * 128 + c]);
    else         g_Wp[(r - 384) * SA + c] = tf32r(proj_w[(r - 384) * 128 + c]);
}
__global__ void prep_bm(const float* __restrict__ mask, const float* __restrict__ bias_table) {
    int w = blockIdx.x, h = blockIdx.y, t = threadIdx.x;
#pragma unroll
    for (int it = 0; it < 16; ++it) {
        int e = t + it * 256;
        int i = e >> 6, j = e & 63;
        int idx = ((i >> 3) - (j >> 3) + 7) * 15 + ((i & 7) - (j & 7) + 7);
        g_BM[(((w << 2) + h) << 12) + e] = mask[w * 4096 + e] + bias_table[idx * 4 + h];
    }
}

__global__ __launch_bounds__(NT, 1)
void winattn_mma(const float* __restrict__ x,
                 const float* __restrict__ qkv_b,
                 const float* __restrict__ proj_b,
                 float* __restrict__ out)
{
    extern __shared__ float sm[];
    const int tid  = threadIdx.x;
    const int wid  = tid >> 5, lane = tid & 31;
    const int g    = lane >> 2, t = lane & 3;
    const int b    = blockIdx.x;
    const uint32_t sb = smem_u32(sm);
    const int t2   = 2 * t;

    // ---- prologue: stream first two W half-chunks, load X ----
    {
#pragma unroll
        for (int e = tid; e < 2112; e += NT)
            cpa16(sb + OPW * 4 + e * 16, (const char*)g_Wq + e * 16);
        CP_COMMIT();
#pragma unroll
        for (int e = tid; e < 2112; e += NT)
            cpa16(sb + (OPW + 8448) * 4 + e * 16, (const char*)(g_Wq + 8448) + e * 16);
        CP_COMMIT();

        const float4* xg = (const float4*)(x + (size_t)b * 8192);
#pragma unroll
        for (int it = 0; it < 8; ++it) {
            int e = tid + it * NT;
            int row = e >> 5, c4 = (e & 31) * 4;
            float4 v = xg[e];
            float4 o; o.x = tf32r(v.x); o.y = tf32r(v.y); o.z = tf32r(v.z); o.w = tf32r(v.w);
            *(float4*)(sm + OX + row * SA + c4) = o;
        }
    }

    const int rg = wid & 3, ch = wid >> 2;   // QKV/proj mapping
    const int hh = wid & 3, rh = wid >> 2;   // attention mapping

    uint32_t af[16][4];                      // X fragments, resident across all 6 chunks

    // ---- QKV: 6 half-chunks (64 cols each), pipelined ----
#pragma unroll
    for (int i = 0; i < 6; ++i) {
        if (i < 5) CP_WAIT(1); else CP_WAIT(0);
        __syncthreads();

        if (i == 0) {    // load A fragments once (X visible after this barrier)
            const float* Ax = sm + OX + (rg * 16) * SA;
#pragma unroll
            for (int kk = 0; kk < 16; ++kk) {
                const float* ap = Ax + g * SA + kk * 8 + t;
                af[kk][0] = __float_as_uint(ap[0]);
                af[kk][1] = __float_as_uint(ap[8 * SA]);
                af[kk][2] = __float_as_uint(ap[4]);
                af[kk][3] = __float_as_uint(ap[8 * SA + 4]);
            }
        }

        float c[4][4] = {};
        const float* B = sm + OPW + (i & 1) * 8448 + (ch * 32) * SA;
#pragma unroll
        for (int kk = 0; kk < 16; ++kk) {
            int k0 = kk * 8;
#pragma unroll
            for (int n = 0; n < 4; ++n) {
                const float* bp = B + (n * 8 + g) * SA + k0 + t;
                mma8(c[n], af[kk][0], af[kk][1], af[kk][2], af[kk][3],
                     __float_as_uint(bp[0]), __float_as_uint(bp[4]));
            }
        }
#pragma unroll
        for (int n = 0; n < 4; ++n) {
            int col = ch * 32 + n * 8 + t2;
            float b0v = __ldg(qkv_b + i * 64 + col);
            float b1v = __ldg(qkv_b + i * 64 + col + 1);
            int tok = rg * 16 + g;
            if (i < 2) {
                int qc = i * 64 + col;
                sm[OQ + tok * SA + qc]           = tf32r((c[n][0] + b0v) * SCALE);
                sm[OQ + tok * SA + qc + 1]       = tf32r((c[n][1] + b1v) * SCALE);
                sm[OQ + (tok + 8) * SA + qc]     = tf32r((c[n][2] + b0v) * SCALE);
                sm[OQ + (tok + 8) * SA + qc + 1] = tf32r((c[n][3] + b1v) * SCALE);
            } else if (i < 4) {
                int kc = (i - 2) * 64 + col;
                sm[OK + tok * SA + kc]           = tf32r(c[n][0] + b0v);
                sm[OK + tok * SA + kc + 1]       = tf32r(c[n][1] + b1v);
                sm[OK + (tok + 8) * SA + kc]     = tf32r(c[n][2] + b0v);
                sm[OK + (tok + 8) * SA + kc + 1] = tf32r(c[n][3] + b1v);
            } else {
                int vd = (i - 4) * 64 + col;
                sm[OVT + vd * SVS + tok]           = tf32r(c[n][0] + b0v);
                sm[OVT + (vd + 1) * SVS + tok]     = tf32r(c[n][1] + b1v);
                sm[OVT + vd * SVS + tok + 8]       = tf32r(c[n][2] + b0v);
                sm[OVT + (vd + 1) * SVS + tok + 8] = tf32r(c[n][3] + b1v);
            }
        }
        __syncthreads();
        if (i + 2 < 6) {
#pragma unroll
            for (int e = tid; e < 2112; e += NT)
                cpa16(sb + (OPW + (i & 1) * 8448) * 4 + e * 16,
                      (const char*)(g_Wq + (i + 2) * 8448) + e * 16);
            CP_COMMIT();
        }
    }

    // ---- scores: warp=(head hh, row-half rh), tile 32x64; C stays in registers ----
    float c[2][8][4] = {};
    {
        const float* A = sm + OQ + (rh * 32) * SA + hh * 32;
        const float* B = sm + OK + hh * 32;
#pragma unroll
        for (int kk = 0; kk < 4; ++kk) {
            int k0 = kk * 8;
            uint32_t a[2][4];
#pragma unroll
            for (int m = 0; m < 2; ++m) {
                const float* ap = A + (m * 16 + g) * SA + k0 + t;
                a[m][0] = __float_as_uint(ap[0]);
                a[m][1] = __float_as_uint(ap[8 * SA]);
                a[m][2] = __float_as_uint(ap[4]);
                a[m][3] = __float_as_uint(ap[8 * SA + 4]);
            }
#pragma unroll
            for (int n = 0; n < 8; ++n) {
                const float* bp = B + (n * 8 + g) * SA + k0 + t;
                uint32_t b0 = __float_as_uint(bp[0]), b1 = __float_as_uint(bp[4]);
#pragma unroll
                for (int m = 0; m < 2; ++m)
                    mma8(c[m][n], a[m][0], a[m][1], a[m][2], a[m][3], b0, b1);
            }
        }
    }
    __syncthreads();    // Q/K reads done -> region reusable for Wp

    // ---- prefetch Wp into OQ/OK region ----
#pragma unroll
    for (int e = tid; e < 4224; e += NT)
        cpa16(sb + OQ * 4 + e * 16, (const char*)g_Wp + e * 16);
    CP_COMMIT();

    // ---- softmax in registers: +BM, quad-lane row reductions ----
    {
        const float* bm = g_BM + ((((b & 63) << 2) + hh) << 12);
        float mx[4] = {-1e30f, -1e30f, -1e30f, -1e30f};
#pragma unroll
        for (int m = 0; m < 2; ++m) {
            int i0 = rh * 32 + m * 16 + g;
#pragma unroll
            for (int n = 0; n < 8; ++n) {
                float2 b0 = *(const float2*)(bm + (i0 << 6) + n * 8 + t2);
                float2 b1 = *(const float2*)(bm + ((i0 + 8) << 6) + n * 8 + t2);
                c[m][n][0] += b0.x; c[m][n][1] += b0.y;
                c[m][n][2] += b1.x; c[m][n][3] += b1.y;
                mx[2*m]   = fmaxf(mx[2*m],   fmaxf(c[m][n][0], c[m][n][1]));
                mx[2*m+1] = fmaxf(mx[2*m+1], fmaxf(c[m][n][2], c[m][n][3]));
            }
        }
#pragma unroll
        for (int s = 0; s < 4; ++s) {
            mx[s] = fmaxf(mx[s], __shfl_xor_sync(0xffffffffu, mx[s], 1));
            mx[s] = fmaxf(mx[s], __shfl_xor_sync(0xffffffffu, mx[s], 2));
        }
        float sum[4] = {0.f, 0.f, 0.f, 0.f};
#pragma unroll
        for (int m = 0; m < 2; ++m)
#pragma unroll
            for (int n = 0; n < 8; ++n) {
                c[m][n][0] = __expf(c[m][n][0] - mx[2*m]);
                c[m][n][1] = __expf(c[m][n][1] - mx[2*m]);
                c[m][n][2] = __expf(c[m][n][2] - mx[2*m+1]);
                c[m][n][3] = __expf(c[m][n][3] - mx[2*m+1]);
                sum[2*m]   += c[m][n][0] + c[m][n][1];
                sum[2*m+1] += c[m][n][2] + c[m][n][3];
            }
#pragma unroll
        for (int s = 0; s < 4; ++s) {
            sum[s] += __shfl_xor_sync(0xffffffffu, sum[s], 1);
            sum[s] += __shfl_xor_sync(0xffffffffu, sum[s], 2);
            sum[s] = 1.0f / sum[s];
        }
#pragma unroll
        for (int m = 0; m < 2; ++m)
#pragma unroll
            for (int n = 0; n < 8; ++n) {
                c[m][n][0] = tf32r(c[m][n][0] * sum[2*m]);
                c[m][n][1] = tf32r(c[m][n][1] * sum[2*m]);
                c[m][n][2] = tf32r(c[m][n][2] * sum[2*m+1]);
                c[m][n][3] = tf32r(c[m][n][3] * sum[2*m+1]);
            }
    }

    // ---- AV: A = P registers (remapped slots: slot t <-> col 2t); B = V^T float2 ----
    {
        float o[2][4][4] = {};
        const float* B = sm + OVT + (hh * 32) * SVS;
#pragma unroll
        for (int kk = 0; kk < 8; ++kk) {
            int k0 = kk * 8 + t2;
#pragma unroll
            for (int n = 0; n < 4; ++n) {
                float2 bv = *(const float2*)(B + (n * 8 + g) * SVS + k0);
#pragma unroll
                for (int m = 0; m < 2; ++m)
                    mma8f(o[m][n], c[m][kk][0], c[m][kk][2], c[m][kk][1], c[m][kk][3],
                          bv.x, bv.y);
            }
        }
#pragma unroll
        for (int m = 0; m < 2; ++m)
#pragma unroll
            for (int n = 0; n < 4; ++n) {
                int i = rh * 32 + m * 16 + g, d = hh * 32 + n * 8 + t2;
                sm[OX + i * SA + d]           = tf32r(o[m][n][0]);
                sm[OX + i * SA + d + 1]       = tf32r(o[m][n][1]);
                sm[OX + (i + 8) * SA + d]     = tf32r(o[m][n][2]);
                sm[OX + (i + 8) * SA + d + 1] = tf32r(o[m][n][3]);
            }
    }
    CP_WAIT(0);
    __syncthreads();

    // ---- proj: warp=(rg, ch), tile 16x64 ----
    {
        float cc[8][4] = {};
        const float* A = sm + OX + (rg * 16) * SA;
        const float* B = sm + OQ + (ch * 64) * SA;
#pragma unroll
        for (int kk = 0; kk < 16; ++kk) {
            int k0 = kk * 8;
            const float* ap = A + g * SA + k0 + t;
            uint32_t a0 = __float_as_uint(ap[0]);
            uint32_t a1 = __float_as_uint(ap[8 * SA]);
            uint32_t a2 = __float_as_uint(ap[4]);
            uint32_t a3 = __float_as_uint(ap[8 * SA + 4]);
#pragma unroll
            for (int n = 0; n < 8; ++n) {
                const float* bp = B + (n * 8 + g) * SA + k0 + t;
                mma8(cc[n], a0, a1, a2, a3, __float_as_uint(bp[0]), __float_as_uint(bp[4]));
            }
        }
#pragma unroll
        for (int n = 0; n < 8; ++n) {
            int col = ch * 64 + n * 8 + t2;
            float pb0 = __ldg(proj_b + col), pb1 = __ldg(proj_b + col + 1);
            int i = rg * 16 + g;
            float2 v0 = make_float2(cc[n][0] + pb0, cc[n][1] + pb1);
            float2 v1 = make_float2(cc[n][2] + pb0, cc[n][3] + pb1);
            *(float2*)(out + ((size_t)b * 64 + i) * 128 + col)     = v0;
            *(float2*)(out + ((size_t)b * 64 + i + 8) * 128 + col) = v1;
        }
    }
}

extern "C" void kernel_launch(void* const* d_in, const int* in_sizes, int n_in,
                              void* d_out, int out_size)
{
    const float* x          = (const float*)d_in[0];
    const float* mask       = (const float*)d_in[1];
    const float* qkv_w      = (const float*)d_in[2];
    const float* qkv_b      = (const float*)d_in[3];
    const float* proj_w     = (const float*)d_in[4];
    const float* proj_b     = (const float*)d_in[5];
    const float* bias_table = (const float*)d_in[6];
    float* out = (float*)d_out;

    prep_w<<<256, 256>>>(qkv_w, proj_w);
    prep_bm<<<dim3(64, 4), 256>>>(mask, bias_table);

    const int smem_bytes = SMF * 4;   // 205824
    cudaFuncSetAttribute(winattn_mma,
                         cudaFuncAttributeMaxDynamicSharedMemorySize, smem_bytes);
    winattn_mma<<<4096, NT, smem_bytes>>>(x, qkv_b, proj_b, out);
}